// round 10
// baseline (speedup 1.0000x reference)
#include <cuda_runtime.h>
#include <math.h>

#define NN 256
#define MM 255

// Scratch (no cudaMalloc allowed)
__device__ float  g_gp[4][NN * NN];   // partial Gram per 64-dim chunk
__device__ float  g_nrm[NN];          // squared norms of stacked rows
__device__ double g_acc;
__device__ int    g_done = 0;         // completion counter (self-resetting)

__device__ __forceinline__ float tanha(float x) {
    float y;
    asm("tanh.approx.f32 %0, %1;" : "=f"(y) : "f"(x));
    return y;
}

// ---------------------------------------------------------------------------
// Kernel 1: blocks 0..127: partial Gram G_ij over a 64-dim chunk.
// 64(i) x 64(j)... no: 64(i) x 32(j) per-thread 4x2? -> tile 64x32? See below:
// tile = 64 i-rows x 32 j-cols, K-chunk 64; grid 4*8*4 = 128 blocks.
// 256 threads, each computes a 4x2 sub-tile: per k-iter 1 LDS.128 (A,
// 2 distinct addrs/warp) + 1 LDS.64 (B) + 8 FFMA -> high ILP.
// Blocks 128..159: squared norms (one warp per row, single pass).
// ---------------------------------------------------------------------------
__global__ void gram_kernel(const float* __restrict__ features) {
    __shared__ float As[64 * 68];   // K-major [k][0..63 rows], stride 68
    __shared__ float Bs[64 * 34];   // K-major [k][0..31 rows], stride 34

    const int bid = blockIdx.x;
    const int tid = threadIdx.x;

    if (bid >= 128) {                       // norms: 32 blocks x 8 rows
        const int w = tid >> 5, lane = tid & 31;
        const int r = ((bid - 128) << 3) + w;
        const float4* row = (const float4*)(features + ((((r & 127) << 1) + (r >> 7)) << 8));
        const float4 a = row[lane];
        const float4 b = row[lane + 32];
        float s = a.x * a.x + a.y * a.y + a.z * a.z + a.w * a.w
                + b.x * b.x + b.y * b.y + b.z * b.z + b.w * b.w;
#pragma unroll
        for (int o = 16; o; o >>= 1) s += __shfl_xor_sync(0xFFFFFFFFu, s, o);
        if (lane == 0) g_nrm[r] = s;
        return;
    }

    // decode: 4 i-tiles(64) x 8 j-tiles(32) x 4 chunks(64 dims)
    const int jt = (bid & 7) << 5;
    const int it = ((bid >> 3) & 3) << 6;
    const int ch = bid >> 5;                // 0..3

    if (bid == 0 && tid == 0) g_acc = 0.0;

    {   // A: 64 rows x 64 dims -> K-major transpose (4 float4 per thread)
        const int r  = tid >> 2;            // 0..63
        const int q0 = tid & 3;
        const int gi = it + r;
        const float* fa = &features[(((gi & 127) << 1) + (gi >> 7)) * 256 + (ch << 6)];
#pragma unroll
        for (int h = 0; h < 4; h++) {
            const int f4 = q0 + (h << 2);   // 0..15
            const float4 a = *(const float4*)&fa[f4 << 2];
            const int k0 = f4 << 2;
            As[(k0 + 0) * 68 + r] = a.x;
            As[(k0 + 1) * 68 + r] = a.y;
            As[(k0 + 2) * 68 + r] = a.z;
            As[(k0 + 3) * 68 + r] = a.w;
        }
    }
    {   // B: 32 rows x 64 dims -> K-major transpose (2 float4 per thread)
        const int r  = tid >> 3;            // 0..31
        const int q0 = tid & 7;
        const int gj = jt + r;
        const float* fb = &features[(((gj & 127) << 1) + (gj >> 7)) * 256 + (ch << 6)];
#pragma unroll
        for (int h = 0; h < 2; h++) {
            const int f4 = q0 + (h << 3);   // 0..15
            const float4 b = *(const float4*)&fb[f4 << 2];
            const int k0 = f4 << 2;
            Bs[(k0 + 0) * 34 + r] = b.x;
            Bs[(k0 + 1) * 34 + r] = b.y;
            Bs[(k0 + 2) * 34 + r] = b.z;
            Bs[(k0 + 3) * 34 + r] = b.w;
        }
    }
    __syncthreads();

    const int a4 = tid >> 4;                // 0..15 -> rows 4*a4
    const int tx = tid & 15;                // cols 2*tx
    float c00 = 0, c01 = 0, c10 = 0, c11 = 0;
    float c20 = 0, c21 = 0, c30 = 0, c31 = 0;
#pragma unroll
    for (int k = 0; k < 64; k++) {
        const float4 av = *(const float4*)&As[k * 68 + (a4 << 2)];
        const float2 bv = *(const float2*)&Bs[k * 34 + (tx << 1)];
        c00 = fmaf(av.x, bv.x, c00);  c01 = fmaf(av.x, bv.y, c01);
        c10 = fmaf(av.y, bv.x, c10);  c11 = fmaf(av.y, bv.y, c11);
        c20 = fmaf(av.z, bv.x, c20);  c21 = fmaf(av.z, bv.y, c21);
        c30 = fmaf(av.w, bv.x, c30);  c31 = fmaf(av.w, bv.y, c31);
    }
    const int r0 = it + (a4 << 2);
    const int c0 = jt + (tx << 1);
    *(float2*)&g_gp[ch][(r0 + 0) * NN + c0] = make_float2(c00, c01);
    *(float2*)&g_gp[ch][(r0 + 1) * NN + c0] = make_float2(c10, c11);
    *(float2*)&g_gp[ch][(r0 + 2) * NN + c0] = make_float2(c20, c21);
    *(float2*)&g_gp[ch][(r0 + 3) * NN + c0] = make_float2(c30, c31);
}

// ---------------------------------------------------------------------------
// Kernel 2: 256 blocks (one per row i) x 256 threads. Unchanged hot path from
// R9 (segmented uniform-bound loops + bit-identical fixup); finalization
// fused: the last block to finish writes out[0] (counter self-resets so the
// kernel stays graph-replayable).
// ---------------------------------------------------------------------------
__global__ void main_kernel(const int* __restrict__ labels, float* __restrict__ out) {
    __shared__ float2 sEQ[NN];     // permuted {E_j, q_j = rh_j - u_j/2}
    __shared__ float4 sKR[NN];     // permuted {z, rh, ladf, 0}
    __shared__ float  sU[NN];      // permuted u_j
    __shared__ int    cntL[8][16], cntK[8][32];
    __shared__ int    sumL[16], sumK[32];
    __shared__ int    histBase[16];
    __shared__ int    BP[10], CP[10], BM[10], CM[10];
    __shared__ int    sNP, sNE;
    __shared__ float  red[256];

    const int i    = blockIdx.x;
    const int tid  = threadIdx.x;
    const int lane = tid & 31;
    const int wid  = tid >> 5;
    const unsigned lt = (1u << lane) - 1u;
    const int li   = labels[i & 127];

    cntK[wid][lane] = 0;
    if (tid < 128) cntL[tid >> 4][tid & 15] = 0;
    __syncthreads();

    // ---- phase 1: per-j basics (j = tid), all loads coalesced ----
    float z = 0.0f, sgn = 0.0f;
    int lad = 15, key = 31;
    if (tid < MM) {
        const int c = tid + (tid >= i);
        float gij = 0.0f;
#pragma unroll
        for (int ch = 0; ch < 4; ch++) gij += g_gp[ch][i * NN + c];
        z = sqrtf(fmaxf(fmaf(-2.0f, gij, g_nrm[i] + g_nrm[c]), 0.0f));
        const int ld = li - labels[c & 127];
        lad = ld < 0 ? -ld : ld;
        key = (lad == 0) ? 0 : (ld > 0 ? lad : 16 + lad);
        sgn = (float)((ld > 0) - (ld < 0));
    }
    const unsigned mL = __match_any_sync(0xFFFFFFFFu, lad);
    const unsigned mK = __match_any_sync(0xFFFFFFFFu, key);
    const int tieL = __popc(mL & lt);
    const int tieK = __popc(mK & lt);
    cntL[wid][lad & 15] = __popc(mL);
    cntK[wid][key]      = __popc(mK);
    __syncthreads();

    if (tid < 16) { int s = 0;
#pragma unroll
        for (int g = 0; g < 8; g++) s += cntL[g][tid];
        sumL[tid] = s; }
    if (tid >= 32 && tid < 64) { int s = 0; const int b = tid - 32;
#pragma unroll
        for (int g = 0; g < 8; g++) s += cntK[g][b];
        sumK[b] = s; }
    __syncthreads();

    if (tid == 0) {
        int run = 0;
#pragma unroll
        for (int b = 0; b < 16; b++) { histBase[b] = run; run += sumL[b]; }
        run = 0;
#pragma unroll
        for (int b = 1; b <= 9; b++) { BP[b] = run; CP[b] = sumK[b]; run += sumK[b]; }
        sNP = run;
#pragma unroll
        for (int b = 1; b <= 9; b++) { BM[b] = run; CM[b] = sumK[16 + b]; run += sumK[16 + b]; }
        sNE = run;
        BP[0] = 0; CP[0] = 0; BM[0] = sNP; CM[0] = 0;
    }
    __syncthreads();

    // ---- phase 2: ranks + deterministic placement ----
    if (tid < MM) {
        int tl = tieL, tk = tieK;
        for (int gg = 0; gg < wid; gg++) { tl += cntL[gg][lad]; tk += cntK[gg][key]; }
        const int rank = histBase[lad] + tl;
        const float rh = 5.0f * (float)rank;     // (rank/delta)/2
        int place;
        if (key == 0)       place = sNE + tk;
        else if (key < 16)  place = BP[key] + tk;
        else                place = BM[key - 16] + tk;
        const float u = sgn * z;
        const float E = __expf(-u);
        sEQ[place] = make_float2(E, fmaf(-0.5f, u, rh));
        sKR[place] = make_float4(z, rh, (float)lad, 0.0f);
        sU[place]  = u;
    }
    __syncthreads();

    // ---- main loop: thread handles permuted k position p = tid ----
    float term = 0.0f;
    if (tid < MM) {
        const float4 kr = sKR[tid];
        const float zk  = kr.x;
        const float rhk = kr.y;
        const int ladk  = (int)kr.z;
        const float epk = __expf(zk);
        const float enk = __expf(-zk);
        const float ckP = fmaf(-0.5f, zk, rhk);
        const float ckM = fmaf( 0.5f, zk, rhk);
        const int NP = sNP, NE = sNE;

        float neg = 1.0f;                   // exact j==k contribution
        float pos = 0.0f;

#pragma unroll 4
        for (int j = 0; j < NP; j++) {      // + segment (uniform bounds)
            const float2 t = sEQ[j];
            const float emd = t.x * epk;
            const float tn  = tanha(t.y - ckP);
            neg += fmaf(emd, tn, emd);
        }
#pragma unroll 4
        for (int j = NP; j < NE; j++) {     // - segment (uniform bounds)
            const float2 t = sEQ[j];
            const float emd = t.x * enk;
            const float tn  = tanha(t.y - ckM);
            neg += fmaf(emd, tn, emd);
        }
#pragma unroll 4
        for (int j = NE; j < MM; j++) {     // zero segment (uniform bounds)
            const float tn = tanha(sEQ[j].y - rhk);
            neg += 1.0f + tn;
        }

        // ---- fixup: subtract eq-run neg terms (bit-identical), add pos ----
        if (ladk != 0) {
            const int loP = BP[ladk], hiP = loP + CP[ladk];
            for (int j = loP; j < hiP; j++) {
                const float2 t = sEQ[j];
                const float emd = t.x * epk;
                const float tn  = tanha(t.y - ckP);
                neg -= fmaf(emd, tn, emd);
                const float d  = sU[j] - zk;
                const float ad = fabsf(d);
                pos += fmaf(ad, tanha(fmaf(0.5f, ad, -0.05f)), ad);
            }
            const int loM = BM[ladk], hiM = loM + CM[ladk];
            for (int j = loM; j < hiM; j++) {
                const float2 t = sEQ[j];
                const float emd = t.x * enk;
                const float tn  = tanha(t.y - ckM);
                neg -= fmaf(emd, tn, emd);
                const float d  = sU[j] + zk;
                const float ad = fabsf(d);
                pos += fmaf(ad, tanha(fmaf(0.5f, ad, -0.05f)), ad);
            }
        } else {
            for (int j = NE; j < MM; j++) { // zero-seg pairs are pos (== 0)
                const float tn = tanha(sEQ[j].y - rhk);
                neg -= 1.0f + tn;           // includes j==k's exact 1; init restores it
            }
        }
        term = pos + logf(neg);
    }
    red[tid] = term;
    __syncthreads();
#pragma unroll
    for (int s = 128; s > 0; s >>= 1) {
        if (tid < s) red[tid] += red[tid + s];
        __syncthreads();
    }
    if (tid == 0) {
        atomicAdd(&g_acc, (double)red[0]);
        __threadfence();
        const int old = atomicAdd(&g_done, 1);
        if (old == NN - 1) {                // last block finalizes
            g_done = 0;                     // reset for next graph replay
            out[0] = (float)(g_acc / (double)(NN * MM));
        }
    }
}

extern "C" void kernel_launch(void* const* d_in, const int* in_sizes, int n_in,
                              void* d_out, int out_size) {
    const float* features = (const float*)d_in[0];   // [128,2,256] f32
    const int*   labels   = (const int*)d_in[1];     // [128,1] i32
    float*       out      = (float*)d_out;           // scalar f32

    gram_kernel<<<160, 256>>>(features);
    main_kernel<<<NN, 256>>>(labels, out);
}